// round 1
// baseline (speedup 1.0000x reference)
#include <cuda_runtime.h>
#include <math.h>

// ---------------- problem constants ----------------
#define BB    2
#define CC    128
#define HH    512
#define WWD   512
#define HWs   (HH*WWD)
#define NWIN  4096          // 64x64 windows per batch
#define NWF   1228          // int(4096*0.3)
#define NSEL  (BB*NWF)      // 2456
#define WIN   64            // tokens per window (8x8)
#define GT    64            // global tokens (8x8 pooled)
#define XST   132           // padded smem row stride (floats) for 128-wide tiles
#define SST   68            // padded stride for 64-wide score tile

// ---------------- scratch (static device memory; no allocs) ----------------
__device__ float g_score[BB*NWIN];
__device__ int   g_sel[NSEL];
__device__ int   g_cnt[BB];
__device__ float g_gx[BB*CC*GT];     // [b][c][t], t = p1*8+p2
__device__ float g_k[BB*GT*CC];      // [b][t][c]
__device__ float g_v[BB*GT*CC];

// ---------------- small helpers ----------------
__device__ __forceinline__ float gelu_exact(float x) {
    return 0.5f * x * (1.0f + erff(x * 0.70710678118654752440f));
}

// Y[r][c] = sum_k Xs[r][k]*W[c][k] (+bias[c]); Xs smem [64][XST], W global [128][128], Y stride ystride
__device__ __forceinline__ void gemm64x128(
    const float* __restrict__ Xs, const float* __restrict__ W,
    const float* __restrict__ bias, float* __restrict__ Y, int ystride, int tid)
{
    int r  = tid >> 2;
    int tc = tid & 3;
    float acc[32];
    #pragma unroll
    for (int j = 0; j < 32; ++j) acc[j] = 0.f;
    const float4* xr = (const float4*)(Xs + r * XST);
    for (int k4 = 0; k4 < 32; ++k4) {
        float4 x = xr[k4];
        #pragma unroll
        for (int j = 0; j < 32; ++j) {
            float4 wv = __ldg(((const float4*)(W + (tc + 4*j) * CC)) + k4);
            acc[j] += x.x*wv.x + x.y*wv.y + x.z*wv.z + x.w*wv.w;
        }
    }
    #pragma unroll
    for (int j = 0; j < 32; ++j) {
        int c = tc + 4*j;
        float bb = bias ? bias[c] : 0.f;
        Y[r * ystride + c] = acc[j] + bb;
    }
}

// S[r][c] = scale * sum_k A[r][k]*Bs[c][k]   (64x64, K=128, both smem stride XST)
__device__ __forceinline__ void attn_scores(
    const float* __restrict__ A, const float* __restrict__ Bs,
    float* __restrict__ S, float scale, int tid)
{
    int r  = tid >> 2;
    int tc = tid & 3;
    float acc[16];
    #pragma unroll
    for (int j = 0; j < 16; ++j) acc[j] = 0.f;
    const float4* ar = (const float4*)(A + r * XST);
    for (int k4 = 0; k4 < 32; ++k4) {
        float4 a = ar[k4];
        #pragma unroll
        for (int j = 0; j < 16; ++j) {
            float4 bv = ((const float4*)(Bs + (tc + 4*j) * XST))[k4];
            acc[j] += a.x*bv.x + a.y*bv.y + a.z*bv.z + a.w*bv.w;
        }
    }
    #pragma unroll
    for (int j = 0; j < 16; ++j) S[r * SST + tc + 4*j] = acc[j] * scale;
}

// row softmax over 64 cols of S [64][SST]
__device__ __forceinline__ void softmax64(float* __restrict__ S, int tid)
{
    int warp = tid >> 5, lane = tid & 31;
    for (int r = warp; r < 64; r += 8) {
        float* row = S + r * SST;
        float v0 = row[lane], v1 = row[lane + 32];
        float m = fmaxf(v0, v1);
        #pragma unroll
        for (int o = 16; o > 0; o >>= 1) m = fmaxf(m, __shfl_xor_sync(0xffffffffu, m, o));
        float e0 = __expf(v0 - m), e1 = __expf(v1 - m);
        float s  = e0 + e1;
        #pragma unroll
        for (int o = 16; o > 0; o >>= 1) s += __shfl_xor_sync(0xffffffffu, s, o);
        float inv = 1.0f / s;
        row[lane]      = e0 * inv;
        row[lane + 32] = e1 * inv;
    }
}

// Y[r][c] (+)= sum_k S[r][k]*V[k][c]   (64x128, K=64). S stride SST, V/Y stride XST.
template <bool ADD>
__device__ __forceinline__ void av_gemm(
    const float* __restrict__ S, const float* __restrict__ V,
    float* __restrict__ Y, int tid)
{
    int c  = tid & 127;
    int r0 = (tid >> 7) * 32;
    float acc[32];
    #pragma unroll
    for (int i = 0; i < 32; ++i) acc[i] = 0.f;
    for (int k = 0; k < 64; ++k) {
        float v = V[k * XST + c];
        #pragma unroll
        for (int i = 0; i < 32; ++i) acc[i] += S[(r0 + i) * SST + k] * v;
    }
    #pragma unroll
    for (int i = 0; i < 32; ++i) {
        if (ADD) Y[(r0 + i) * XST + c] += acc[i];
        else     Y[(r0 + i) * XST + c]  = acc[i];
    }
}

// ---------------- kernel 1: window uncertainty scores (+ zero counters) ----------------
__global__ __launch_bounds__(256) void score_kernel(const float* __restrict__ unc)
{
    int idx = blockIdx.x * blockDim.x + threadIdx.x;
    if (idx == 0) { g_cnt[0] = 0; g_cnt[1] = 0; }
    if (idx >= BB * NWIN) return;
    int b = idx / NWIN, w = idx % NWIN;
    int wh = w >> 6, ww = w & 63;
    const float* p = unc + (size_t)b * HWs + (wh * 8) * WWD + ww * 8;
    float rs[8];
    #pragma unroll
    for (int r = 0; r < 8; ++r) {
        const float* q = p + r * WWD;
        rs[r] = ((q[0]+q[1]) + (q[2]+q[3])) + ((q[4]+q[5]) + (q[6]+q[7]));
    }
    float s = ((rs[0]+rs[1]) + (rs[2]+rs[3])) + ((rs[4]+rs[5]) + (rs[6]+rs[7]));
    g_score[idx] = s * (1.0f / 64.0f);
}

// ---------------- kernel 2: top-NWF selection by rank counting ----------------
__global__ __launch_bounds__(256) void select_kernel()
{
    __shared__ float sc[NWIN];
    int b = blockIdx.y;
    for (int i = threadIdx.x; i < NWIN; i += 256) sc[i] = g_score[b * NWIN + i];
    __syncthreads();
    int w = blockIdx.x * 256 + threadIdx.x;
    float mine = sc[w];
    int rank = 0;
    for (int j = 0; j < NWIN; ++j) {
        float v = sc[j];
        rank += (v > mine) || (v == mine && j < w);
    }
    if (rank < NWF) {
        int slot = atomicAdd(&g_cnt[b], 1);
        g_sel[b * NWF + slot] = w;
    }
}

// ---------------- kernel 3: 64x64 average pooling -> gx[b][c][t] ----------------
__global__ __launch_bounds__(256) void pool_kernel(const float* __restrict__ fm)
{
    int o  = blockIdx.x;            // b*CC*GT outputs
    int t  = o & 63;
    int bc = o >> 6;                // b*CC + c
    int p1 = t >> 3, p2 = t & 7;
    const float* base = fm + (size_t)bc * HWs + p1 * 64 * WWD + p2 * 64;
    int row  = threadIdx.x >> 2;
    int cseg = threadIdx.x & 3;
    const float* q = base + row * WWD + cseg * 16;
    float s = 0.f;
    #pragma unroll
    for (int i = 0; i < 16; ++i) s += q[i];
    __shared__ float red[256];
    red[threadIdx.x] = s;
    __syncthreads();
    for (int st = 128; st > 0; st >>= 1) {
        if (threadIdx.x < st) red[threadIdx.x] += red[threadIdx.x + st];
        __syncthreads();
    }
    if (threadIdx.x == 0) g_gx[o] = red[0] * (1.0f / 4096.0f);
}

// ---------------- kernel 4: global k,v = g @ kv_g_w.T ----------------
__global__ __launch_bounds__(256) void kv_kernel(const float* __restrict__ kvw)
{
    extern __shared__ float sm[];
    float* gs = sm;                 // [64][XST]: g[t][c] = gx[b][c][t]
    int b = blockIdx.x, tid = threadIdx.x;
    for (int i = tid; i < GT * CC; i += 256) {
        int t = i & 63, c = i >> 6;
        gs[t * XST + c] = g_gx[(b * CC + c) * GT + t];
    }
    __syncthreads();
    gemm64x128(gs, kvw,            nullptr, g_k + b * GT * CC, CC, tid);
    gemm64x128(gs, kvw + CC * CC,  nullptr, g_v + b * GT * CC, CC, tid);
}

// ---------------- kernel 5: fully fused per-window pipeline ----------------
__global__ __launch_bounds__(256) void fused_kernel(
    const float* __restrict__ fm, float* __restrict__ out,
    const float* __restrict__ Wq,
    const float* __restrict__ W0, const float* __restrict__ b0,
    const float* __restrict__ Wqkv,
    const float* __restrict__ Wp, const float* __restrict__ bp)
{
    extern __shared__ float sm[];
    float* Xs = sm;                    // wf tile      [64][XST]
    float* A  = sm + 1 * 64 * XST;     // q / scratch  [64][XST]
    float* Bk = sm + 2 * 64 * XST;     // k tile       [64][XST]
    float* Cv = sm + 3 * 64 * XST;     // v tile       [64][XST]
    float* S  = sm + 4 * 64 * XST;     // scores       [64][SST]

    int s   = blockIdx.x;
    int b   = s / NWF;
    int w   = g_sel[s];
    int wh  = w >> 6, ww = w & 63;
    int tid = threadIdx.x;
    const float scale = 0.08838834764831845f;   // 128^-0.5

    // P1: gather window from feature_map (+ load global k,v)
    for (int i = tid; i < WIN * CC; i += 256) {
        int c = i >> 6, t = i & 63;
        int tr = t >> 3, tc2 = t & 7;
        Xs[t * XST + c] = fm[(size_t)(b * CC + c) * HWs + (wh * 8 + tr) * WWD + (ww * 8 + tc2)];
    }
    for (int i = tid; i < GT * CC; i += 256) {
        int t = i >> 7, c = i & 127;
        Bk[t * XST + c] = g_k[b * GT * CC + i];
        Cv[t * XST + c] = g_v[b * GT * CC + i];
    }
    __syncthreads();

    // P2: q = wf @ Wq^T
    gemm64x128(Xs, Wq, nullptr, A, XST, tid);
    __syncthreads();

    // P3-P5: cross attention vs 64 global tokens; wf += attn @ v
    attn_scores(A, Bk, S, scale, tid);
    __syncthreads();
    softmax64(S, tid);
    __syncthreads();
    av_gemm<true>(S, Cv, Xs, tid);
    __syncthreads();

    // P6: wf += gelu(wf @ W0^T + b0)
    gemm64x128(Xs, W0, b0, A, XST, tid);
    __syncthreads();
    for (int i = tid; i < WIN * CC; i += 256) {
        int t = i >> 7, c = i & 127;
        Xs[t * XST + c] += gelu_exact(A[t * XST + c]);
    }
    __syncthreads();

    // P7: qkv projections
    gemm64x128(Xs, Wqkv,            nullptr, A,  XST, tid);
    gemm64x128(Xs, Wqkv + 1*CC*CC,  nullptr, Bk, XST, tid);
    gemm64x128(Xs, Wqkv + 2*CC*CC,  nullptr, Cv, XST, tid);
    __syncthreads();

    // P8: window self-attention
    attn_scores(A, Bk, S, scale, tid);
    __syncthreads();
    softmax64(S, tid);
    __syncthreads();
    av_gemm<false>(S, Cv, A, tid);      // A = attn @ v   [q][c]
    __syncthreads();

    // P9: wf[i][j] += av[j%64][2*i + j/64]   (the swapaxes(1,2).reshape)
    for (int i = tid; i < WIN * CC; i += 256) {
        int t = i >> 7, c = i & 127;
        Xs[t * XST + c] += A[(c & 63) * XST + (2 * t + (c >> 6))];
    }
    __syncthreads();

    // P10: wf += gelu(wf @ Wp^T + bp)
    gemm64x128(Xs, Wp, bp, A, XST, tid);
    __syncthreads();
    for (int i = tid; i < WIN * CC; i += 256) {
        int t = i >> 7, c = i & 127;
        Xs[t * XST + c] += gelu_exact(A[t * XST + c]);
    }
    __syncthreads();

    // P11: scatter back into output
    for (int i = tid; i < WIN * CC; i += 256) {
        int c = i >> 6, t = i & 63;
        int tr = t >> 3, tc2 = t & 7;
        out[(size_t)(b * CC + c) * HWs + (wh * 8 + tr) * WWD + (ww * 8 + tc2)] = Xs[t * XST + c];
    }
}

// ---------------- launch ----------------
extern "C" void kernel_launch(void* const* d_in, const int* in_sizes, int n_in,
                              void* d_out, int out_size)
{
    const float* fm    = (const float*)d_in[0];
    const float* unc   = (const float*)d_in[1];
    const float* q_g_w = (const float*)d_in[2];
    const float* kv_w  = (const float*)d_in[3];
    const float* w0    = (const float*)d_in[4];
    const float* b0    = (const float*)d_in[5];
    const float* wqkv  = (const float*)d_in[6];
    const float* wp    = (const float*)d_in[7];
    const float* bp    = (const float*)d_in[8];
    float* out = (float*)d_out;

    const int KV_SMEM    = 64 * XST * (int)sizeof(float);                       // ~33 KB
    const int FUSED_SMEM = (4 * 64 * XST + 64 * SST) * (int)sizeof(float);      // ~149 KB

    cudaFuncSetAttribute(kv_kernel,    cudaFuncAttributeMaxDynamicSharedMemorySize, KV_SMEM);
    cudaFuncSetAttribute(fused_kernel, cudaFuncAttributeMaxDynamicSharedMemorySize, FUSED_SMEM);

    // out = feature_map (untouched windows), selected windows overwritten by fused_kernel
    cudaMemcpyAsync(out, fm, sizeof(float) * (size_t)BB * CC * HH * WWD,
                    cudaMemcpyDeviceToDevice);

    score_kernel<<<(BB * NWIN + 255) / 256, 256>>>(unc);
    select_kernel<<<dim3(16, BB), 256>>>();
    pool_kernel<<<BB * CC * GT, 256>>>(fm);
    kv_kernel<<<BB, 256, KV_SMEM>>>(kv_w);
    fused_kernel<<<NSEL, 256, FUSED_SMEM>>>(fm, out, q_g_w, w0, b0, wqkv, wp, bp);
}

// round 2
// speedup vs baseline: 4.2516x; 4.2516x over previous
#include <cuda_runtime.h>
#include <math.h>

// ---------------- problem constants ----------------
#define BB    2
#define CC    128
#define HH    512
#define WWD   512
#define HWs   (HH*WWD)
#define NWIN  4096          // 64x64 windows per batch
#define NWF   1228          // int(4096*0.3)
#define NSEL  (BB*NWF)      // 2456
#define WIN   64            // tokens per window (8x8)
#define GT    64            // global tokens (8x8 pooled)
#define XST   132           // padded smem row stride (floats), 16B aligned, conflict-free
#define SST   68            // padded stride for 64-wide score tile
#define WST   132           // weight stage row stride

// ---------------- scratch (static device memory; no allocs) ----------------
__device__ float g_score[BB*NWIN];
__device__ int   g_sel[NSEL];
__device__ int   g_cnt[BB];
__device__ float g_gx[BB*CC*GT];     // [b][c][t]
__device__ float g_k[BB*GT*CC];      // [b][t][c]
__device__ float g_v[BB*GT*CC];

// ---------------- low-level helpers ----------------
#define FMA2(d,a,b) asm("fma.rn.f32x2 %0, %1, %2, %0;" : "+l"(d) : "l"(a), "l"(b))

__device__ __forceinline__ float hsum2(unsigned long long v) {
    return __uint_as_float((unsigned)v) + __uint_as_float((unsigned)(v >> 32));
}
__device__ __forceinline__ unsigned long long dup2(float s) {
    unsigned long long d;
    asm("mov.b64 %0, {%1,%1};" : "=l"(d) : "r"(__float_as_uint(s)));
    return d;
}
__device__ __forceinline__ void cp16(float* dst_smem, const float* src) {
    unsigned saddr = (unsigned)__cvta_generic_to_shared(dst_smem);
    asm volatile("cp.async.cg.shared.global [%0], [%1], 16;" :: "r"(saddr), "l"(src));
}
__device__ __forceinline__ void cp_commit() { asm volatile("cp.async.commit_group;"); }
template<int N> __device__ __forceinline__ void cp_wait() {
    asm volatile("cp.async.wait_group %0;" :: "n"(N));
}
__device__ __forceinline__ float gelu_exact(float x) {
    return 0.5f * x * (1.0f + erff(x * 0.70710678118654752440f));
}

// ---------------- GEMM: Y[64][128] = Xs @ W^T (+bias), W staged via cp.async ----------------
// Weight chunk stage: 32 channels (rows of W), 128 k each, into buf[32][WST]
__device__ __forceinline__ void stage_w(const float* __restrict__ Wg, int chunk,
                                        float* __restrict__ buf, int tid)
{
    int row = tid >> 3;           // 0..31 (channel within chunk)
    int seg = tid & 7;            // 8 x float4 segments, x4
    const float* src = Wg + (chunk * 32 + row) * CC + seg * 4;
    float* dst = buf + row * WST + seg * 4;
    #pragma unroll
    for (int q = 0; q < 4; ++q) cp16(dst + 32 * q, src + 32 * q);
}

// Compute one 32-channel chunk. Thread tile: 2 rows x 4 cols (cols c0+cg+8j).
__device__ __forceinline__ void gemm_chunk(const float* __restrict__ Xs,
                                           const float* __restrict__ Wt,
                                           const float* __restrict__ bias,
                                           float* __restrict__ Y, int ystride,
                                           int c0, int tid)
{
    int rlo = tid >> 3, cg = tid & 7;
    int r0 = 2 * rlo;
    unsigned long long acc[8] = {0,0,0,0,0,0,0,0};
    const ulonglong2* x0 = (const ulonglong2*)(Xs + r0 * XST);
    const ulonglong2* x1 = (const ulonglong2*)(Xs + (r0 + 1) * XST);
    #pragma unroll 8
    for (int k4 = 0; k4 < 32; ++k4) {
        ulonglong2 xa = x0[k4];
        ulonglong2 xb = x1[k4];
        #pragma unroll
        for (int j = 0; j < 4; ++j) {
            ulonglong2 wv = ((const ulonglong2*)(Wt + (cg + 8 * j) * WST))[k4];
            FMA2(acc[2*j],   xa.x, wv.x);
            FMA2(acc[2*j],   xa.y, wv.y);
            FMA2(acc[2*j+1], xb.x, wv.x);
            FMA2(acc[2*j+1], xb.y, wv.y);
        }
    }
    #pragma unroll
    for (int j = 0; j < 4; ++j) {
        int c = c0 + cg + 8 * j;
        float bv = bias ? __ldg(bias + c) : 0.f;
        Y[r0 * ystride + c]       = hsum2(acc[2*j])   + bv;
        Y[(r0 + 1) * ystride + c] = hsum2(acc[2*j+1]) + bv;
    }
}

// Full 64x128 GEMM with double-buffered weight staging. Needs team-wide entry/exit sync.
__device__ __forceinline__ void gemm_ws(const float* __restrict__ Xs,
                                        const float* __restrict__ Wg,
                                        const float* __restrict__ bias,
                                        float* __restrict__ Y, int ystride,
                                        float* __restrict__ Wb, int tid)
{
    stage_w(Wg, 0, Wb, tid); cp_commit();
    #pragma unroll
    for (int i = 0; i < 4; ++i) {
        if (i < 3) { stage_w(Wg, i + 1, Wb + ((i + 1) & 1) * 32 * WST, tid); cp_commit(); cp_wait<1>(); }
        else       { cp_wait<0>(); }
        __syncthreads();
        gemm_chunk(Xs, Wb + (i & 1) * 32 * WST, bias, Y, ystride, i * 32, tid);
        __syncthreads();
    }
}

// ---------------- S[64][64] = scale * A @ Bs^T (K=128) ----------------
__device__ __forceinline__ void attn_scores(const float* __restrict__ A,
                                            const float* __restrict__ Bs,
                                            float* __restrict__ S, float scale, int tid)
{
    int rlo = tid >> 3, cg = tid & 7;
    int r0 = 2 * rlo;
    unsigned long long acc[16] = {};
    const ulonglong2* a0 = (const ulonglong2*)(A + r0 * XST);
    const ulonglong2* a1 = (const ulonglong2*)(A + (r0 + 1) * XST);
    #pragma unroll 4
    for (int k4 = 0; k4 < 32; ++k4) {
        ulonglong2 xa = a0[k4];
        ulonglong2 xb = a1[k4];
        #pragma unroll
        for (int j = 0; j < 8; ++j) {
            ulonglong2 bv = ((const ulonglong2*)(Bs + (cg + 8 * j) * XST))[k4];
            FMA2(acc[2*j],   xa.x, bv.x);
            FMA2(acc[2*j],   xa.y, bv.y);
            FMA2(acc[2*j+1], xb.x, bv.x);
            FMA2(acc[2*j+1], xb.y, bv.y);
        }
    }
    #pragma unroll
    for (int j = 0; j < 8; ++j) {
        int c = cg + 8 * j;
        S[r0 * SST + c]       = hsum2(acc[2*j])   * scale;
        S[(r0 + 1) * SST + c] = hsum2(acc[2*j+1]) * scale;
    }
}

// ---------------- row softmax over 64 cols ----------------
__device__ __forceinline__ void softmax64(float* __restrict__ S, int tid)
{
    int warp = tid >> 5, lane = tid & 31;
    for (int r = warp; r < 64; r += 8) {
        float* row = S + r * SST;
        float v0 = row[lane], v1 = row[lane + 32];
        float m = fmaxf(v0, v1);
        #pragma unroll
        for (int o = 16; o > 0; o >>= 1) m = fmaxf(m, __shfl_xor_sync(0xffffffffu, m, o));
        float e0 = __expf(v0 - m), e1 = __expf(v1 - m);
        float s  = e0 + e1;
        #pragma unroll
        for (int o = 16; o > 0; o >>= 1) s += __shfl_xor_sync(0xffffffffu, s, o);
        float inv = 1.0f / s;
        row[lane]      = e0 * inv;
        row[lane + 32] = e1 * inv;
    }
}

// ---------------- Y[64][128] (+)= S[64][64] @ V[64][128] ----------------
// Thread tile: 2 rows x 16 cols (cols 4cg+32jj+{0..3}), packed over column pairs.
template <bool ADD>
__device__ __forceinline__ void av_gemm(const float* __restrict__ S,
                                        const float* __restrict__ V,
                                        float* __restrict__ Y, int tid)
{
    int rg = tid >> 3, cg = tid & 7;
    int r0 = 2 * rg;
    unsigned long long acc[16] = {};   // [row 0/1 -> 0..7 / 8..15][jj*2+pairHalf]
    #pragma unroll 4
    for (int k = 0; k < 64; ++k) {
        unsigned long long s0d = dup2(S[r0 * SST + k]);
        unsigned long long s1d = dup2(S[(r0 + 1) * SST + k]);
        #pragma unroll
        for (int jj = 0; jj < 4; ++jj) {
            ulonglong2 vv = *(const ulonglong2*)(V + k * XST + 4 * cg + 32 * jj);
            FMA2(acc[jj*2],     s0d, vv.x);
            FMA2(acc[jj*2+1],   s0d, vv.y);
            FMA2(acc[8+jj*2],   s1d, vv.x);
            FMA2(acc[8+jj*2+1], s1d, vv.y);
        }
    }
    #pragma unroll
    for (int jj = 0; jj < 4; ++jj) {
        #pragma unroll
        for (int p = 0; p < 2; ++p) {
            int c = 4 * cg + 32 * jj + 2 * p;
            unsigned long long a0v = acc[jj*2+p], a1v = acc[8+jj*2+p];
            float a0lo = __uint_as_float((unsigned)a0v), a0hi = __uint_as_float((unsigned)(a0v >> 32));
            float a1lo = __uint_as_float((unsigned)a1v), a1hi = __uint_as_float((unsigned)(a1v >> 32));
            if (ADD) {
                Y[r0*XST + c]     += a0lo; Y[r0*XST + c + 1]     += a0hi;
                Y[(r0+1)*XST + c] += a1lo; Y[(r0+1)*XST + c + 1] += a1hi;
            } else {
                Y[r0*XST + c]     = a0lo;  Y[r0*XST + c + 1]     = a0hi;
                Y[(r0+1)*XST + c] = a1lo;  Y[(r0+1)*XST + c + 1] = a1hi;
            }
        }
    }
}

// ---------------- kernel 1: window uncertainty scores (+ zero counters) ----------------
__global__ __launch_bounds__(256) void score_kernel(const float* __restrict__ unc)
{
    int idx = blockIdx.x * blockDim.x + threadIdx.x;
    if (idx == 0) { g_cnt[0] = 0; g_cnt[1] = 0; }
    if (idx >= BB * NWIN) return;
    int b = idx / NWIN, w = idx % NWIN;
    int wh = w >> 6, ww = w & 63;
    const float* p = unc + (size_t)b * HWs + (wh * 8) * WWD + ww * 8;
    float rs[8];
    #pragma unroll
    for (int r = 0; r < 8; ++r) {
        const float* q = p + r * WWD;
        rs[r] = ((q[0]+q[1]) + (q[2]+q[3])) + ((q[4]+q[5]) + (q[6]+q[7]));
    }
    float s = ((rs[0]+rs[1]) + (rs[2]+rs[3])) + ((rs[4]+rs[5]) + (rs[6]+rs[7]));
    g_score[idx] = s * (1.0f / 64.0f);
}

// ---------------- kernel 2: top-NWF selection by rank counting ----------------
__global__ __launch_bounds__(256) void select_kernel()
{
    __shared__ float sc[NWIN];
    int b = blockIdx.y;
    for (int i = threadIdx.x; i < NWIN; i += 256) sc[i] = g_score[b * NWIN + i];
    __syncthreads();
    int w = blockIdx.x * 256 + threadIdx.x;
    float mine = sc[w];
    int rank = 0;
    for (int j = 0; j < NWIN; ++j) {
        float v = sc[j];
        rank += (v > mine) || (v == mine && j < w);
    }
    if (rank < NWF) {
        int slot = atomicAdd(&g_cnt[b], 1);
        g_sel[b * NWF + slot] = w;
    }
}

// ---------------- kernel 3: 64x64 average pooling -> gx[b][c][t] ----------------
__global__ __launch_bounds__(256) void pool_kernel(const float* __restrict__ fm)
{
    int o  = blockIdx.x;            // b*CC*GT outputs
    int t  = o & 63;
    int bc = o >> 6;
    int p1 = t >> 3, p2 = t & 7;
    const float* base = fm + (size_t)bc * HWs + p1 * 64 * WWD + p2 * 64;
    int row  = threadIdx.x >> 2;
    int cseg = threadIdx.x & 3;
    const float* q = base + row * WWD + cseg * 16;
    float s = 0.f;
    #pragma unroll
    for (int i = 0; i < 16; ++i) s += q[i];
    __shared__ float red[256];
    red[threadIdx.x] = s;
    __syncthreads();
    for (int st = 128; st > 0; st >>= 1) {
        if (threadIdx.x < st) red[threadIdx.x] += red[threadIdx.x + st];
        __syncthreads();
    }
    if (threadIdx.x == 0) g_gx[o] = red[0] * (1.0f / 4096.0f);
}

// ---------------- kernel 4: global k,v = g @ kv_g_w.T (16 blocks) ----------------
__global__ __launch_bounds__(256) void kv_kernel(const float* __restrict__ kvw)
{
    __shared__ float gs[GT * XST];
    int b = blockIdx.y, chunk = blockIdx.x;     // 8 chunks of 32 output channels
    int tid = threadIdx.x;
    for (int i = tid; i < GT * CC; i += 256) {
        int t = i & 63, c = i >> 6;
        gs[t * XST + c] = g_gx[(b * CC + c) * GT + t];
    }
    __syncthreads();
    int t = tid & 63;
    int qg = tid >> 6;                          // 0..3 -> 8 channels each
    float acc[8] = {0,0,0,0,0,0,0,0};
    const float4* xr = (const float4*)(gs + t * XST);
    for (int k4 = 0; k4 < 32; ++k4) {
        float4 x = xr[k4];
        #pragma unroll
        for (int j = 0; j < 8; ++j) {
            int oc = chunk * 32 + qg * 8 + j;
            float4 wv = __ldg(((const float4*)(kvw + oc * CC)) + k4);
            acc[j] += x.x*wv.x + x.y*wv.y + x.z*wv.z + x.w*wv.w;
        }
    }
    #pragma unroll
    for (int j = 0; j < 8; ++j) {
        int oc = chunk * 32 + qg * 8 + j;
        if (oc < CC) g_k[(b * GT + t) * CC + oc]      = acc[j];
        else         g_v[(b * GT + t) * CC + oc - CC] = acc[j];
    }
}

// ---------------- kernel 5: fully fused per-window pipeline ----------------
__global__ __launch_bounds__(256, 1) void fused_kernel(
    const float* __restrict__ fm, float* __restrict__ out,
    const float* __restrict__ Wq,
    const float* __restrict__ W0, const float* __restrict__ b0,
    const float* __restrict__ Wqkv,
    const float* __restrict__ Wp, const float* __restrict__ bp)
{
    extern __shared__ float sm[];
    float* Xs = sm;                          // wf tile      [64][XST]
    float* A  = sm + 1 * 64 * XST;           // q / scratch  [64][XST]
    float* Bk = sm + 2 * 64 * XST;           // k tile       [64][XST]
    float* Cv = sm + 3 * 64 * XST;           // v tile       [64][XST]
    float* S  = sm + 4 * 64 * XST;           // scores       [64][SST]
    float* Wb = S + 64 * SST;                // weight double-buffer [2][32][WST]

    int s   = blockIdx.x;
    int b   = s / NWF;
    int w   = g_sel[s];
    int wh  = w >> 6, ww = w & 63;
    int tid = threadIdx.x;
    const float scale = 0.08838834764831845f;   // 128^-0.5

    // P1: gather window + load global k,v
    for (int i = tid; i < WIN * CC; i += 256) {
        int c = i >> 6, t = i & 63;
        int tr = t >> 3, tc2 = t & 7;
        Xs[t * XST + c] = fm[(size_t)(b * CC + c) * HWs + (wh * 8 + tr) * WWD + (ww * 8 + tc2)];
    }
    for (int i = tid; i < GT * CC; i += 256) {
        int t = i >> 7, c = i & 127;
        Bk[t * XST + c] = g_k[b * GT * CC + i];
        Cv[t * XST + c] = g_v[b * GT * CC + i];
    }
    __syncthreads();

    // P2: q = wf @ Wq^T
    gemm_ws(Xs, Wq, nullptr, A, XST, Wb, tid);

    // P3-P5: cross attention vs 64 global tokens; wf += attn @ v
    attn_scores(A, Bk, S, scale, tid);
    __syncthreads();
    softmax64(S, tid);
    __syncthreads();
    av_gemm<true>(S, Cv, Xs, tid);
    __syncthreads();

    // P6: wf += gelu(wf @ W0^T + b0)
    gemm_ws(Xs, W0, b0, A, XST, Wb, tid);
    for (int i = tid; i < WIN * CC; i += 256) {
        int t = i >> 7, c = i & 127;
        Xs[t * XST + c] += gelu_exact(A[t * XST + c]);
    }
    __syncthreads();

    // P7: qkv projections
    gemm_ws(Xs, Wqkv,            nullptr, A,  XST, Wb, tid);
    gemm_ws(Xs, Wqkv + 1*CC*CC,  nullptr, Bk, XST, Wb, tid);
    gemm_ws(Xs, Wqkv + 2*CC*CC,  nullptr, Cv, XST, Wb, tid);

    // P8: window self-attention
    attn_scores(A, Bk, S, scale, tid);
    __syncthreads();
    softmax64(S, tid);
    __syncthreads();
    av_gemm<false>(S, Cv, A, tid);      // A = attn @ v   [q][c]
    __syncthreads();

    // P9: wf[i][j] += av[j%64][2*i + j/64]   (swapaxes(1,2).reshape)
    for (int i = tid; i < WIN * CC; i += 256) {
        int t = i >> 7, c = i & 127;
        Xs[t * XST + c] += A[(c & 63) * XST + (2 * t + (c >> 6))];
    }
    __syncthreads();

    // P10: wf += gelu(wf @ Wp^T + bp)
    gemm_ws(Xs, Wp, bp, A, XST, Wb, tid);
    for (int i = tid; i < WIN * CC; i += 256) {
        int t = i >> 7, c = i & 127;
        Xs[t * XST + c] += gelu_exact(A[t * XST + c]);
    }
    __syncthreads();

    // P11: scatter back into output
    for (int i = tid; i < WIN * CC; i += 256) {
        int c = i >> 6, t = i & 63;
        int tr = t >> 3, tc2 = t & 7;
        out[(size_t)(b * CC + c) * HWs + (wh * 8 + tr) * WWD + (ww * 8 + tc2)] = Xs[t * XST + c];
    }
}

// ---------------- launch ----------------
extern "C" void kernel_launch(void* const* d_in, const int* in_sizes, int n_in,
                              void* d_out, int out_size)
{
    const float* fm    = (const float*)d_in[0];
    const float* unc   = (const float*)d_in[1];
    const float* q_g_w = (const float*)d_in[2];
    const float* kv_w  = (const float*)d_in[3];
    const float* w0    = (const float*)d_in[4];
    const float* b0    = (const float*)d_in[5];
    const float* wqkv  = (const float*)d_in[6];
    const float* wp    = (const float*)d_in[7];
    const float* bp    = (const float*)d_in[8];
    float* out = (float*)d_out;

    const int FUSED_SMEM = (4 * 64 * XST + 64 * SST + 2 * 32 * WST) * (int)sizeof(float); // ~182 KB
    cudaFuncSetAttribute(fused_kernel, cudaFuncAttributeMaxDynamicSharedMemorySize, FUSED_SMEM);

    // out = feature_map (untouched windows), selected windows overwritten by fused_kernel
    cudaMemcpyAsync(out, fm, sizeof(float) * (size_t)BB * CC * HH * WWD,
                    cudaMemcpyDeviceToDevice);

    score_kernel<<<(BB * NWIN + 255) / 256, 256>>>(unc);
    select_kernel<<<dim3(16, BB), 256>>>();
    pool_kernel<<<BB * CC * GT, 256>>>(fm);
    kv_kernel<<<dim3(8, BB), 256>>>(kv_w);
    fused_kernel<<<NSEL, 256, FUSED_SMEM>>>(fm, out, q_g_w, w0, b0, wqkv, wp, bp);
}

// round 4
// speedup vs baseline: 5.2611x; 1.2375x over previous
#include <cuda_runtime.h>
#include <math.h>

// ---------------- problem constants ----------------
#define BB    2
#define CC    128
#define HH    512
#define WWD   512
#define HWs   (HH*WWD)
#define NWIN  4096          // 64x64 windows per batch
#define NWF   1228          // int(4096*0.3)
#define NSEL  (BB*NWF)      // 2456
#define WIN   64            // tokens per window (8x8)
#define GT    64            // global tokens (8x8 pooled)
#define XST   132           // padded smem row stride (floats)
#define SST   68            // padded stride for 64-wide score tile
#define WST   132           // weight stage row stride

// ---------------- scratch (static device memory; no allocs) ----------------
__device__ float g_score[BB*NWIN];
__device__ int   g_sel[NSEL];
__device__ int   g_cnt[BB];
__device__ float g_gx[BB*CC*GT];     // [b][c][t]
__device__ float g_k[BB*GT*CC];      // [b][t][c]
__device__ float g_v[BB*GT*CC];

// ---------------- low-level helpers ----------------
#define FMA2(d,a,b) asm("fma.rn.f32x2 %0, %1, %2, %0;" : "+l"(d) : "l"(a), "l"(b))

__device__ __forceinline__ float hsum2(unsigned long long v) {
    return __uint_as_float((unsigned)v) + __uint_as_float((unsigned)(v >> 32));
}
__device__ __forceinline__ unsigned long long dup2(float s) {
    unsigned long long d;
    asm("mov.b64 %0, {%1,%1};" : "=l"(d) : "r"(__float_as_uint(s)));
    return d;
}
__device__ __forceinline__ void cp16(float* dst_smem, const float* src) {
    unsigned saddr = (unsigned)__cvta_generic_to_shared(dst_smem);
    asm volatile("cp.async.cg.shared.global [%0], [%1], 16;" :: "r"(saddr), "l"(src));
}
__device__ __forceinline__ void cp_commit() { asm volatile("cp.async.commit_group;"); }
template<int N> __device__ __forceinline__ void cp_wait() {
    asm volatile("cp.async.wait_group %0;" :: "n"(N));
}
__device__ __forceinline__ float gelu_exact(float x) {
    return 0.5f * x * (1.0f + erff(x * 0.70710678118654752440f));
}

// ---------------- weight stage: 64 out-channels (rows of W) into buf[64][WST] ----------------
__device__ __forceinline__ void stage_w64(const float* __restrict__ Wg, int half,
                                          float* __restrict__ buf, int tid)
{
    int row = tid >> 2;           // 0..63
    int q   = tid & 3;
    const float* src = Wg + (half * 64 + row) * CC + q * 4;
    float* dst = buf + row * WST + q * 4;
    #pragma unroll
    for (int m = 0; m < 8; ++m) cp16(dst + 16 * m, src + 16 * m);
}

// ---------------- GEMM half: Y[64][c0..c0+63] = Xs @ Wt^T (+bias) ----------------
// warp = 8-row group (x loads broadcast); lane covers cols {c0+lane, c0+lane+32}
__device__ __forceinline__ void gemm_half(const float* __restrict__ Xs,
                                          const float* __restrict__ Wt,
                                          const float* __restrict__ bias,
                                          float* __restrict__ Y, int ystride,
                                          int c0, int tid)
{
    int lane = tid & 31, warp = tid >> 5;
    int r0 = warp * 8;
    unsigned long long acc[16] = {};      // [row 0..7][col 0..1]
    const float* xb = Xs + r0 * XST;
    const ulonglong2* w0p = (const ulonglong2*)(Wt + lane * WST);
    const ulonglong2* w1p = (const ulonglong2*)(Wt + (lane + 32) * WST);
    #pragma unroll 4
    for (int k4 = 0; k4 < 32; ++k4) {
        ulonglong2 w0 = w0p[k4];
        ulonglong2 w1 = w1p[k4];
        #pragma unroll
        for (int r = 0; r < 8; ++r) {
            ulonglong2 xv = ((const ulonglong2*)(xb + r * XST))[k4];
            FMA2(acc[2*r],   xv.x, w0.x); FMA2(acc[2*r],   xv.y, w0.y);
            FMA2(acc[2*r+1], xv.x, w1.x); FMA2(acc[2*r+1], xv.y, w1.y);
        }
    }
    float b0v = 0.f, b1v = 0.f;
    if (bias) { b0v = __ldg(bias + c0 + lane); b1v = __ldg(bias + c0 + lane + 32); }
    #pragma unroll
    for (int r = 0; r < 8; ++r) {
        Y[(r0 + r) * ystride + c0 + lane]      = hsum2(acc[2*r])   + b0v;
        Y[(r0 + r) * ystride + c0 + lane + 32] = hsum2(acc[2*r+1]) + b1v;
    }
}

// Full 64x128 GEMM; weight chunks overlapped via cp.async. Team-wide sync inside.
__device__ __forceinline__ void gemm_ws(const float* __restrict__ Xs,
                                        const float* __restrict__ Wg,
                                        const float* __restrict__ bias,
                                        float* __restrict__ Y, int ystride,
                                        float* __restrict__ Wb, int tid)
{
    stage_w64(Wg, 0, Wb, tid);              cp_commit();
    stage_w64(Wg, 1, Wb + 64 * WST, tid);   cp_commit();
    cp_wait<1>(); __syncthreads();
    gemm_half(Xs, Wb, bias, Y, ystride, 0, tid);
    cp_wait<0>(); __syncthreads();
    gemm_half(Xs, Wb + 64 * WST, bias, Y, ystride, 64, tid);
    __syncthreads();
}

// ---------------- S[64][64] = scale * A @ Bs^T (K=128) ----------------
__device__ __forceinline__ void attn_scores(const float* __restrict__ A,
                                            const float* __restrict__ Bs,
                                            float* __restrict__ S, float scale, int tid)
{
    int rlo = tid >> 3, cg = tid & 7;
    int r0 = 2 * rlo;
    unsigned long long acc[16] = {};
    const ulonglong2* a0 = (const ulonglong2*)(A + r0 * XST);
    const ulonglong2* a1 = (const ulonglong2*)(A + (r0 + 1) * XST);
    #pragma unroll 4
    for (int k4 = 0; k4 < 32; ++k4) {
        ulonglong2 xa = a0[k4];
        ulonglong2 xb = a1[k4];
        #pragma unroll
        for (int j = 0; j < 8; ++j) {
            ulonglong2 bv = ((const ulonglong2*)(Bs + (cg + 8 * j) * XST))[k4];
            FMA2(acc[2*j],   xa.x, bv.x);
            FMA2(acc[2*j],   xa.y, bv.y);
            FMA2(acc[2*j+1], xb.x, bv.x);
            FMA2(acc[2*j+1], xb.y, bv.y);
        }
    }
    #pragma unroll
    for (int j = 0; j < 8; ++j) {
        int c = cg + 8 * j;
        S[r0 * SST + c]       = hsum2(acc[2*j])   * scale;
        S[(r0 + 1) * SST + c] = hsum2(acc[2*j+1]) * scale;
    }
}

// ---------------- row softmax over 64 cols ----------------
__device__ __forceinline__ void softmax64(float* __restrict__ S, int tid)
{
    int warp = tid >> 5, lane = tid & 31;
    for (int r = warp; r < 64; r += 8) {
        float* row = S + r * SST;
        float v0 = row[lane], v1 = row[lane + 32];
        float m = fmaxf(v0, v1);
        #pragma unroll
        for (int o = 16; o > 0; o >>= 1) m = fmaxf(m, __shfl_xor_sync(0xffffffffu, m, o));
        float e0 = __expf(v0 - m), e1 = __expf(v1 - m);
        float s  = e0 + e1;
        #pragma unroll
        for (int o = 16; o > 0; o >>= 1) s += __shfl_xor_sync(0xffffffffu, s, o);
        float inv = 1.0f / s;
        row[lane]      = e0 * inv;
        row[lane + 32] = e1 * inv;
    }
}

// ---------------- Y[64][128] (+)= S[64][64] @ V[64][128] ----------------
// warp = 8-row group; lane covers 4 cols (lane*4..lane*4+3). S broadcast, V coalesced.
template <bool ADD>
__device__ __forceinline__ void av_gemm(const float* __restrict__ S,
                                        const float* __restrict__ V,
                                        float* __restrict__ Y, int tid)
{
    int lane = tid & 31, warp = tid >> 5;
    int r0 = warp * 8;
    unsigned long long acc[16] = {};      // [row 0..7][col-pair 0..1]
    #pragma unroll 2
    for (int kk = 0; kk < 16; ++kk) {     // k in groups of 4
        float4 sr[8];
        #pragma unroll
        for (int r = 0; r < 8; ++r) sr[r] = ((const float4*)(S + (r0 + r) * SST))[kk];
        #pragma unroll
        for (int kq = 0; kq < 4; ++kq) {
            int k = kk * 4 + kq;
            ulonglong2 vv = *(const ulonglong2*)(V + k * XST + lane * 4);
            #pragma unroll
            for (int r = 0; r < 8; ++r) {
                float sv = (kq == 0) ? sr[r].x : (kq == 1) ? sr[r].y : (kq == 2) ? sr[r].z : sr[r].w;
                unsigned long long sd = dup2(sv);
                FMA2(acc[2*r],   sd, vv.x);
                FMA2(acc[2*r+1], sd, vv.y);
            }
        }
    }
    #pragma unroll
    for (int r = 0; r < 8; ++r) {
        float* yr = Y + (r0 + r) * XST + lane * 4;
        unsigned long long a0v = acc[2*r], a1v = acc[2*r+1];
        float v0 = __uint_as_float((unsigned)a0v), v1 = __uint_as_float((unsigned)(a0v >> 32));
        float v2 = __uint_as_float((unsigned)a1v), v3 = __uint_as_float((unsigned)(a1v >> 32));
        if (ADD) { yr[0] += v0; yr[1] += v1; yr[2] += v2; yr[3] += v3; }
        else     { yr[0]  = v0; yr[1]  = v1; yr[2]  = v2; yr[3]  = v3; }
    }
}

// ---------------- kernel 1: window uncertainty scores (+ zero counters) ----------------
__global__ __launch_bounds__(256) void score_kernel(const float* __restrict__ unc)
{
    int idx = blockIdx.x * blockDim.x + threadIdx.x;
    if (idx == 0) { g_cnt[0] = 0; g_cnt[1] = 0; }
    if (idx >= BB * NWIN) return;
    int b = idx / NWIN, w = idx % NWIN;
    int wh = w >> 6, ww = w & 63;
    const float* p = unc + (size_t)b * HWs + (wh * 8) * WWD + ww * 8;
    float rs[8];
    #pragma unroll
    for (int r = 0; r < 8; ++r) {
        const float* q = p + r * WWD;
        rs[r] = ((q[0]+q[1]) + (q[2]+q[3])) + ((q[4]+q[5]) + (q[6]+q[7]));
    }
    float s = ((rs[0]+rs[1]) + (rs[2]+rs[3])) + ((rs[4]+rs[5]) + (rs[6]+rs[7]));
    g_score[idx] = s * (1.0f / 64.0f);
}

// ---------------- kernel 2: top-NWF selection by rank counting ----------------
__global__ __launch_bounds__(256) void select_kernel()
{
    __shared__ float sc[NWIN];
    int b = blockIdx.y;
    for (int i = threadIdx.x; i < NWIN; i += 256) sc[i] = g_score[b * NWIN + i];
    __syncthreads();
    int w = blockIdx.x * 256 + threadIdx.x;
    float mine = sc[w];
    int rank = 0;
    for (int j = 0; j < NWIN; ++j) {
        float v = sc[j];
        rank += (v > mine) || (v == mine && j < w);
    }
    if (rank < NWF) {
        int slot = atomicAdd(&g_cnt[b], 1);
        g_sel[b * NWF + slot] = w;
    }
}

// ---------------- kernel 3: 64x64 average pooling -> gx[b][c][t] ----------------
__global__ __launch_bounds__(256) void pool_kernel(const float* __restrict__ fm)
{
    int o  = blockIdx.x;
    int t  = o & 63;
    int bc = o >> 6;
    int p1 = t >> 3, p2 = t & 7;
    const float* base = fm + (size_t)bc * HWs + p1 * 64 * WWD + p2 * 64;
    int row  = threadIdx.x >> 2;
    int cseg = threadIdx.x & 3;
    const float* q = base + row * WWD + cseg * 16;
    float s = 0.f;
    #pragma unroll
    for (int i = 0; i < 16; ++i) s += q[i];
    __shared__ float red[256];
    red[threadIdx.x] = s;
    __syncthreads();
    for (int st = 128; st > 0; st >>= 1) {
        if (threadIdx.x < st) red[threadIdx.x] += red[threadIdx.x + st];
        __syncthreads();
    }
    if (threadIdx.x == 0) g_gx[o] = red[0] * (1.0f / 4096.0f);
}

// ---------------- kernel 4: global k,v = g @ kv_g_w.T ----------------
__global__ __launch_bounds__(256) void kv_kernel(const float* __restrict__ kvw)
{
    __shared__ float gs[GT * XST];
    int b = blockIdx.y, chunk = blockIdx.x;
    int tid = threadIdx.x;
    for (int i = tid; i < GT * CC; i += 256) {
        int t = i & 63, c = i >> 6;
        gs[t * XST + c] = g_gx[(b * CC + c) * GT + t];
    }
    __syncthreads();
    int t = tid & 63;
    int qg = tid >> 6;
    float acc[8] = {0,0,0,0,0,0,0,0};
    const float4* xr = (const float4*)(gs + t * XST);
    for (int k4 = 0; k4 < 32; ++k4) {
        float4 x = xr[k4];
        #pragma unroll
        for (int j = 0; j < 8; ++j) {
            int oc = chunk * 32 + qg * 8 + j;
            float4 wv = __ldg(((const float4*)(kvw + oc * CC)) + k4);
            acc[j] += x.x*wv.x + x.y*wv.y + x.z*wv.z + x.w*wv.w;
        }
    }
    #pragma unroll
    for (int j = 0; j < 8; ++j) {
        int oc = chunk * 32 + qg * 8 + j;
        if (oc < CC) g_k[(b * GT + t) * CC + oc]      = acc[j];
        else         g_v[(b * GT + t) * CC + oc - CC] = acc[j];
    }
}

// ---------------- kernel 5: fully fused per-window pipeline ----------------
__global__ __launch_bounds__(256, 1) void fused_kernel(
    const float* __restrict__ fm, float* __restrict__ out,
    const float* __restrict__ Wq,
    const float* __restrict__ W0, const float* __restrict__ b0,
    const float* __restrict__ Wqkv,
    const float* __restrict__ Wp, const float* __restrict__ bp)
{
    extern __shared__ float sm[];
    float* Xs = sm;                          // wf tile      [64][XST]
    float* A  = sm + 1 * 64 * XST;           // q / scratch  [64][XST]
    float* Bk = sm + 2 * 64 * XST;           // k tile       [64][XST]
    float* Cv = sm + 3 * 64 * XST;           // v tile       [64][XST]
    float* S  = sm + 4 * 64 * XST;           // scores       [64][SST]
    float* Wb = S + 64 * SST;                // weight chunks [2][64][WST]

    int s   = blockIdx.x;
    int b   = s / NWF;
    int w   = g_sel[s];
    int wh  = w >> 6, ww = w & 63;
    int tid = threadIdx.x;
    const float scale = 0.08838834764831845f;   // 128^-0.5

    // P1: gather window + load global k,v
    for (int i = tid; i < WIN * CC; i += 256) {
        int c = i >> 6, t = i & 63;
        int tr = t >> 3, tc2 = t & 7;
        Xs[t * XST + c] = fm[(size_t)(b * CC + c) * HWs + (wh * 8 + tr) * WWD + (ww * 8 + tc2)];
    }
    for (int i = tid; i < GT * CC; i += 256) {
        int t = i >> 7, c = i & 127;
        Bk[t * XST + c] = g_k[b * GT * CC + i];
        Cv[t * XST + c] = g_v[b * GT * CC + i];
    }
    __syncthreads();

    // P2: q = wf @ Wq^T
    gemm_ws(Xs, Wq, nullptr, A, XST, Wb, tid);

    // P3-P5: cross attention vs 64 global tokens; wf += attn @ v
    attn_scores(A, Bk, S, scale, tid);
    __syncthreads();
    softmax64(S, tid);
    __syncthreads();
    av_gemm<true>(S, Cv, Xs, tid);
    __syncthreads();

    // P6: wf += gelu(wf @ W0^T + b0)
    gemm_ws(Xs, W0, b0, A, XST, Wb, tid);
    for (int i = tid; i < WIN * CC; i += 256) {
        int t = i >> 7, c = i & 127;
        Xs[t * XST + c] += gelu_exact(A[t * XST + c]);
    }
    __syncthreads();

    // P7: qkv projections
    gemm_ws(Xs, Wqkv,            nullptr, A,  XST, Wb, tid);
    gemm_ws(Xs, Wqkv + 1*CC*CC,  nullptr, Bk, XST, Wb, tid);
    gemm_ws(Xs, Wqkv + 2*CC*CC,  nullptr, Cv, XST, Wb, tid);

    // P8: window self-attention
    attn_scores(A, Bk, S, scale, tid);
    __syncthreads();
    softmax64(S, tid);
    __syncthreads();
    av_gemm<false>(S, Cv, A, tid);      // A = attn @ v   [q][c]
    __syncthreads();

    // P9: wf[i][j] += av[j%64][2*i + j/64]   (swapaxes(1,2).reshape)
    for (int i = tid; i < WIN * CC; i += 256) {
        int t = i >> 7, c = i & 127;
        Xs[t * XST + c] += A[(c & 63) * XST + (2 * t + (c >> 6))];
    }
    __syncthreads();

    // P10: wf += gelu(wf @ Wp^T + bp)
    gemm_ws(Xs, Wp, bp, A, XST, Wb, tid);
    for (int i = tid; i < WIN * CC; i += 256) {
        int t = i >> 7, c = i & 127;
        Xs[t * XST + c] += gelu_exact(A[t * XST + c]);
    }
    __syncthreads();

    // P11: scatter back into output
    for (int i = tid; i < WIN * CC; i += 256) {
        int c = i >> 6, t = i & 63;
        int tr = t >> 3, tc2 = t & 7;
        out[(size_t)(b * CC + c) * HWs + (wh * 8 + tr) * WWD + (ww * 8 + tc2)] = Xs[t * XST + c];
    }
}

// ---------------- launch ----------------
extern "C" void kernel_launch(void* const* d_in, const int* in_sizes, int n_in,
                              void* d_out, int out_size)
{
    const float* fm    = (const float*)d_in[0];
    const float* unc   = (const float*)d_in[1];
    const float* q_g_w = (const float*)d_in[2];
    const float* kv_w  = (const float*)d_in[3];
    const float* w0    = (const float*)d_in[4];
    const float* b0    = (const float*)d_in[5];
    const float* wqkv  = (const float*)d_in[6];
    const float* wp    = (const float*)d_in[7];
    const float* bp    = (const float*)d_in[8];
    float* out = (float*)d_out;

    const int FUSED_SMEM = (4 * 64 * XST + 64 * SST + 2 * 64 * WST) * (int)sizeof(float); // ~215 KB
    cudaFuncSetAttribute(fused_kernel, cudaFuncAttributeMaxDynamicSharedMemorySize, FUSED_SMEM);

    // out = feature_map (untouched windows), selected windows overwritten by fused_kernel
    cudaMemcpyAsync(out, fm, sizeof(float) * (size_t)BB * CC * HH * WWD,
                    cudaMemcpyDeviceToDevice);

    score_kernel<<<(BB * NWIN + 255) / 256, 256>>>(unc);
    select_kernel<<<dim3(16, BB), 256>>>();
    pool_kernel<<<BB * CC * GT, 256>>>(fm);
    kv_kernel<<<dim3(8, BB), 256>>>(kv_w);
    fused_kernel<<<NSEL, 256, FUSED_SMEM>>>(fm, out, q_g_w, w0, b0, wqkv, wp, bp);
}